// round 8
// baseline (speedup 1.0000x reference)
#include <cuda_runtime.h>

#define BB 4
#define NN 4096
#define KK 64
#define MM (NN*KK)
#define C1 64
#define C2 128
#define C3 256

__device__ int    g_swap;
__device__ int    g_idx[BB*NN*KK];
__device__ float  g_y1[(size_t)BB*C1*MM];
__device__ float  g_h1[(size_t)BB*C1*MM];
__device__ float  g_y2[(size_t)BB*C2*MM];
__device__ float  g_h2[(size_t)BB*C2*MM];
__device__ float  g_y3[(size_t)BB*C3*MM];
__device__ double g_sd[3][BB*C3*2];
__device__ float  g_ms[3][BB*C3*2];
__device__ float  g_w1t[C1*C2], g_w2t[C2*C3];

__global__ void k_detect(const float* __restrict__ a) {
    __shared__ int neg;
    if (threadIdx.x == 0) neg = 0;
    __syncthreads();
    int f = 0;
    for (int i = threadIdx.x; i < BB*3*NN; i += 256) if (a[i] < 0.f) f = 1;
    if (f) neg = 1;
    __syncthreads();
    if (threadIdx.x == 0) g_swap = neg;   // first big array has negatives -> it is feats
}

__global__ void k_prep(const float* __restrict__ W1, const float* __restrict__ W2) {
    int t = blockIdx.x * blockDim.x + threadIdx.x;
    if (t < 3*BB*C3*2) (&g_sd[0][0])[t] = 0.0;
    if (t < C2*C1) g_w1t[(t % C1)*C2 + (t / C1)] = W1[t];
    if (t < C3*C2) g_w2t[(t % C2)*C3 + (t / C2)] = W2[t];
}

// serial KNN, 1 thread/point: first K valid (ascending j), fill = smallest valid j
__global__ void k_knn2(const float* __restrict__ cA, const float* __restrict__ cB) {
    const float* coords = g_swap ? cB : cA;
    const int pid = blockIdx.x * blockDim.x + threadIdx.x;
    if (pid >= BB*NN) return;
    const int b = pid >> 12, n = pid & (NN - 1);
    const float* cb = coords + (size_t)b * 3 * NN;
    const float px = cb[n], py = cb[NN+n], pz = cb[2*NN+n];
    int* out = g_idx + (size_t)pid * KK;
    int cnt = 0, j0 = -1;
    for (int j = 0; j < NN; j++) {
        float dx = cb[j] - px, dy = cb[NN+j] - py, dz = cb[2*NN+j] - pz;
        float d2 = __fadd_rn(__fadd_rn(__fmul_rn(dx,dx), __fmul_rn(dy,dy)), __fmul_rn(dz,dz));
        if (!(d2 > 0.04f)) {
            if (j0 < 0) j0 = j;
            if (cnt < KK) out[cnt] = j;
            if (++cnt >= KK) break;
        }
    }
    for (int t = cnt; t < KK; t++) out[t] = j0;
}

__device__ __forceinline__ float fangle(float ax,float ay,float az,
                                        float bx,float by,float bz) {
    float cx = ay*bz - az*by, cy = az*bx - ax*bz, cz = ax*by - ay*bx;
    return atan2f(sqrtf(cx*cx + cy*cy + cz*cz), ax*bx + ay*by + az*bz);
}

__global__ void k_feat(const float* __restrict__ cA, const float* __restrict__ cB,
                       const float* __restrict__ W0) {
    const float* coords = g_swap ? cB : cA;
    const float* feats  = g_swap ? cA : cB;
    __shared__ float sW[C1*10];
    for (int i = threadIdx.x; i < C1*10; i += blockDim.x) sW[i] = W0[i];
    __syncthreads();
    const int gid = blockIdx.x * blockDim.x + threadIdx.x;
    const int b = gid >> 18, m = gid & (MM - 1);
    const int n = m >> 6, k = m & 63;
    const float* cb = coords + (size_t)b * 3 * NN;
    const float* fb = feats  + (size_t)b * 3 * NN;
    const float px = cb[n], py = cb[NN+n], pz = cb[2*NN+n];
    const float ax = fb[n], ay = fb[NN+n], az = fb[2*NN+n];
    const int j = g_idx[((size_t)(b*NN + n))*KK + k];
    const float dx = cb[j]-px, dy = cb[NN+j]-py, dz = cb[2*NN+j]-pz;
    const float bx = fb[j], by = fb[NN+j], bz = fb[2*NN+j];
    float f[10];
    f[0]=px; f[1]=py; f[2]=pz; f[3]=dx; f[4]=dy; f[5]=dz;
    if (j == n) {
        // self column: d is exactly (+0,+0,+0). XLA's sum starts from a +0 init,
        // so its dot is +0 -> arctan2(0,+0)=0 ALWAYS. Emulate that explicitly
        // (naive compiled dot gives -0 when all normal comps are negative -> pi).
        f[6] = 0.f; f[7] = 0.f; f[9] = 0.f;
    } else {
        f[6] = fangle(ax,ay,az, dx,dy,dz);
        f[7] = fangle(bx,by,bz, dx,dy,dz);
        f[9] = sqrtf(dx*dx + dy*dy + dz*dz);
    }
    f[8] = fangle(ax,ay,az, bx,by,bz);
    float* yp = g_y1 + (size_t)b*C1*MM + m;
#pragma unroll
    for (int o = 0; o < C1; o++) {
        float a = 0.f;
#pragma unroll
        for (int c = 0; c < 10; c++) a = fmaf(sW[o*10 + c], f[c], a);
        yp[(size_t)o * MM] = a;
    }
}

template<int C, int L>
__global__ void k_stats() {
    __shared__ double rs[256], rq[256];
    const float* X = (L == 0) ? g_y1 : (L == 1) ? g_y2 : g_y3;
    const int id = blockIdx.x, q4 = id & 3, c = (id >> 2) % C, b = id / (4*C);
    const float* x = X + ((size_t)(b*C) + c)*MM + (size_t)q4 * (MM/4);
    float s = 0.f, ss = 0.f;
    for (int i = threadIdx.x; i < MM/16; i += 256) {
        float4 v = ((const float4*)x)[i];
        s  += (v.x + v.y) + (v.z + v.w);
        ss += (v.x*v.x + v.y*v.y) + (v.z*v.z + v.w*v.w);
    }
    rs[threadIdx.x] = (double)s; rq[threadIdx.x] = (double)ss; __syncthreads();
    for (int st = 128; st; st >>= 1) {
        if (threadIdx.x < st) { rs[threadIdx.x] += rs[threadIdx.x+st]; rq[threadIdx.x] += rq[threadIdx.x+st]; }
        __syncthreads();
    }
    if (threadIdx.x == 0) {
        atomicAdd(&g_sd[L][(b*C + c)*2 + 0], rs[0]);
        atomicAdd(&g_sd[L][(b*C + c)*2 + 1], rq[0]);
    }
}

template<int C, int L>
__global__ void k_final() {
    int t = blockIdx.x * blockDim.x + threadIdx.x;
    if (t >= BB*C) return;
    const double inv = 1.0 / (double)MM;
    double mean = g_sd[L][2*t] * inv;
    double var  = g_sd[L][2*t+1] * inv - mean*mean;
    if (var < 0.0) var = 0.0;
    g_ms[L][2*t]   = (float)mean;
    g_ms[L][2*t+1] = (float)(1.0 / sqrt(var + 1e-5));
}

template<int C, int L>
__global__ void k_norm() {
    const float* X = (L == 0) ? g_y1 : g_y2;
    float*       H = (L == 0) ? g_h1 : g_h2;
    size_t i4 = (size_t)blockIdx.x * 256 + threadIdx.x;
    int ch = (int)(i4 >> 16);
    float mean = g_ms[L][ch*2], istd = g_ms[L][ch*2 + 1];
    float4 v = ((const float4*)X)[i4];
    float4 h;
    h.x = fmaxf(0.f, (v.x - mean) * istd);
    h.y = fmaxf(0.f, (v.y - mean) * istd);
    h.z = fmaxf(0.f, (v.z - mean) * istd);
    h.w = fmaxf(0.f, (v.w - mean) * istd);
    ((float4*)H)[i4] = h;
}

template<int CIN, int COUT, int LID>
__global__ void __launch_bounds__(256) k_gemm() {
    constexpr int ROWS = COUT / 16;
    __shared__ float sX[16*64];
    __shared__ float sW[16*COUT];
    const float* X  = (LID == 1) ? g_h1  : g_h2;
    const float* WT = (LID == 1) ? g_w1t : g_w2t;
    float*       Y  = (LID == 1) ? g_y2  : g_y3;
    const int tid = threadIdx.x, tx = tid & 15, ty = tid >> 4;
    const int b = blockIdx.x >> 12, tn = blockIdx.x & 4095;
    const float* Xb = X + (size_t)b * CIN * MM;
    float acc[ROWS][4];
#pragma unroll
    for (int r = 0; r < ROWS; r++)
        { acc[r][0]=0.f; acc[r][1]=0.f; acc[r][2]=0.f; acc[r][3]=0.f; }
    for (int k0 = 0; k0 < CIN; k0 += 16) {
        *(float4*)(sX + ty*64 + tx*4) =
            *(const float4*)(Xb + (size_t)(k0 + ty)*MM + tn*64 + tx*4);
#pragma unroll
        for (int i = 0; i < COUT*16/256; i++)
            sW[i*256 + tid] = WT[k0*COUT + i*256 + tid];
        __syncthreads();
#pragma unroll
        for (int kc = 0; kc < 16; kc++) {
            float4 xv = *(const float4*)(sX + kc*64 + tx*4);
#pragma unroll
            for (int r = 0; r < ROWS; r++) {
                float w = sW[kc*COUT + ty*ROWS + r];
                acc[r][0] = fmaf(w, xv.x, acc[r][0]);
                acc[r][1] = fmaf(w, xv.y, acc[r][1]);
                acc[r][2] = fmaf(w, xv.z, acc[r][2]);
                acc[r][3] = fmaf(w, xv.w, acc[r][3]);
            }
        }
        __syncthreads();
    }
    const int m0 = tn*64 + tx*4;
#pragma unroll
    for (int r = 0; r < ROWS; r++) {
        const int o = ty*ROWS + r;
        *(float4*)(Y + ((size_t)(b*COUT) + o)*MM + m0) =
            make_float4(acc[r][0], acc[r][1], acc[r][2], acc[r][3]);
    }
}

__global__ void k_maxout(float* __restrict__ out) {
    int t = blockIdx.x * 256 + threadIdx.x;
    if (t >= BB*C3*NN) return;
    int bo = t >> 12, n = t & 4095;
    float mean = g_ms[2][bo*2], istd = g_ms[2][bo*2 + 1];
    const float4* row = (const float4*)(g_y3 + (size_t)bo*MM + (size_t)n*64);
    float mx = 0.f;
#pragma unroll
    for (int i = 0; i < 16; i++) {
        float4 v = row[i];
        mx = fmaxf(mx, fmaxf(fmaxf((v.x-mean)*istd, (v.y-mean)*istd),
                             fmaxf((v.z-mean)*istd, (v.w-mean)*istd)));
    }
    out[t] = fmaxf(mx, 0.f);
}

extern "C" void kernel_launch(void* const* d_in, const int* in_sizes, int n_in,
                              void* d_out, int out_size) {
    const float *big0 = nullptr, *big1 = nullptr, *W0 = nullptr, *W1 = nullptr, *W2 = nullptr;
    for (int i = 0; i < n_in; i++) {
        int sz = in_sizes[i];
        const float* p = (const float*)d_in[i];
        if (sz == BB*3*NN) { if (!big0) big0 = p; else big1 = p; }
        else if (sz == 64*10)   W0 = p;
        else if (sz == 128*64)  W1 = p;
        else if (sz == 256*128) W2 = p;
    }
    float* out = (float*)d_out;

    k_detect<<<1, 256>>>(big0);
    k_prep<<<128, 256>>>(W1, W2);
    k_knn2<<<(BB*NN + 127)/128, 128>>>(big0, big1);
    k_feat<<<(BB*MM)/128, 128>>>(big0, big1, W0);

    k_stats<C1, 0><<<BB*C1*4, 256>>>();
    k_final<C1, 0><<<1, 256>>>();
    k_norm<C1, 0><<<(BB*C1*MM/4)/256, 256>>>();

    k_gemm<C1, C2, 1><<<BB*NN, 256>>>();
    k_stats<C2, 1><<<BB*C2*4, 256>>>();
    k_final<C2, 1><<<2, 256>>>();
    k_norm<C2, 1><<<(BB*C2*MM/4)/256, 256>>>();

    k_gemm<C2, C3, 2><<<BB*NN, 256>>>();
    k_stats<C3, 2><<<BB*C3*4, 256>>>();
    k_final<C3, 2><<<4, 256>>>();

    k_maxout<<<(BB*C3*NN)/256, 256>>>(out);
}

// round 10
// speedup vs baseline: 1.8890x; 1.8890x over previous
#include <cuda_runtime.h>
#include <cstdint>

#define BB 4
#define NN 4096
#define KK 64
#define MM (NN*KK)
#define C1 64
#define C2 128
#define C3 256

// ---------------- scratch ---------------------------------------------------
__device__ int    g_swap;
__device__ int    g_idx[BB*NN*KK];
__device__ float  g_y1[(size_t)BB*C1*MM];          // 256 MB raw layer-0 out
__device__ float  g_y2[(size_t)BB*C2*MM];          // 512 MB raw layer-1 out
__device__ float  g_ymax[(size_t)BB*NN*C3];        // 16 MB  max_k raw layer-2, [b][n][cout]
__device__ double g_sd[3][BB*C3*2];                // sum,sumsq per layer
__device__ float  g_ms[3][BB*C3*2];                // mean,istd per layer

// ---------------- helpers ----------------------------------------------------
__device__ __forceinline__ uint32_t f2tf32(float f) {
    uint32_t r; asm("cvt.rna.tf32.f32 %0, %1;" : "=r"(r) : "f"(f)); return r;
}
__device__ __forceinline__ void mma1688(float* d, const uint32_t* a, const uint32_t* b) {
    asm volatile(
      "mma.sync.aligned.m16n8k8.row.col.f32.tf32.tf32.f32 "
      "{%0,%1,%2,%3}, {%4,%5,%6,%7}, {%8,%9}, {%0,%1,%2,%3};"
      : "+f"(d[0]), "+f"(d[1]), "+f"(d[2]), "+f"(d[3])
      : "r"(a[0]), "r"(a[1]), "r"(a[2]), "r"(a[3]), "r"(b[0]), "r"(b[1]));
}

// ---------------- input detect / prep ---------------------------------------
__global__ void k_detect(const float* __restrict__ a) {
    __shared__ int neg;
    if (threadIdx.x == 0) neg = 0;
    __syncthreads();
    int f = 0;
    for (int i = threadIdx.x; i < BB*3*NN; i += 256) if (a[i] < 0.f) f = 1;
    if (f) neg = 1;
    __syncthreads();
    if (threadIdx.x == 0) g_swap = neg;
}

__global__ void k_prep() {
    int t = blockIdx.x * blockDim.x + threadIdx.x;
    if (t < 3*BB*C3*2) (&g_sd[0][0])[t] = 0.0;
}

// ---------------- KNN: warp-ballot per point ---------------------------------
__global__ void k_knn(const float* __restrict__ cA, const float* __restrict__ cB) {
    const float* coords = g_swap ? cB : cA;
    __shared__ float sx[NN], sy[NN], sz[NN];
    const int warp = threadIdx.x >> 5, lane = threadIdx.x & 31;
    const int pid = blockIdx.x * 8 + warp;
    const int b = pid >> 12, n = pid & (NN - 1);
    const float* cb = coords + (size_t)b * 3 * NN;
    for (int i = threadIdx.x; i < NN; i += blockDim.x) {
        sx[i] = cb[i]; sy[i] = cb[NN + i]; sz[i] = cb[2*NN + i];
    }
    __syncthreads();
    const float px = sx[n], py = sy[n], pz = sz[n];
    int cnt = 0, j0 = 0;
    int* out = g_idx + (size_t)pid * KK;
    for (int base = 0; base < NN; base += 32) {
        int j = base + lane;
        float dx = sx[j] - px, dy = sy[j] - py, dz = sz[j] - pz;
        float d2 = __fadd_rn(__fadd_rn(__fmul_rn(dx,dx), __fmul_rn(dy,dy)), __fmul_rn(dz,dz));
        bool valid = !(d2 > 0.04f);
        unsigned m = __ballot_sync(0xffffffffu, valid);
        if (cnt == 0 && m) j0 = base + (__ffs(m) - 1);
        int pos = cnt + __popc(m & ((1u << lane) - 1u));
        if (valid && pos < KK) out[pos] = j;
        cnt += __popc(m);
        if (cnt >= KK) break;
    }
    if (cnt < KK)
        for (int t = cnt + lane; t < KK; t += 32) out[t] = j0;
}

// ---------------- features + layer-0 (10 -> 64) -----------------------------
__device__ __forceinline__ float fangle(float ax,float ay,float az,
                                        float bx,float by,float bz) {
    float cx = ay*bz - az*by, cy = az*bx - ax*bz, cz = ax*by - ay*bx;
    return atan2f(sqrtf(cx*cx + cy*cy + cz*cz), ax*bx + ay*by + az*bz);
}

__global__ void k_feat(const float* __restrict__ cA, const float* __restrict__ cB,
                       const float* __restrict__ W0) {
    const float* coords = g_swap ? cB : cA;
    const float* feats  = g_swap ? cA : cB;
    __shared__ float sW[C1*10];
    for (int i = threadIdx.x; i < C1*10; i += blockDim.x) sW[i] = W0[i];
    __syncthreads();
    const int gid = blockIdx.x * blockDim.x + threadIdx.x;
    const int b = gid >> 18, m = gid & (MM - 1);
    const int n = m >> 6, k = m & 63;
    const float* cb = coords + (size_t)b * 3 * NN;
    const float* fb = feats  + (size_t)b * 3 * NN;
    const float px = cb[n], py = cb[NN+n], pz = cb[2*NN+n];
    const float ax = fb[n], ay = fb[NN+n], az = fb[2*NN+n];
    const int j = g_idx[((size_t)(b*NN + n))*KK + k];
    const float dx = cb[j]-px, dy = cb[NN+j]-py, dz = cb[2*NN+j]-pz;
    const float bx = fb[j], by = fb[NN+j], bz = fb[2*NN+j];
    float f[10];
    f[0]=px; f[1]=py; f[2]=pz; f[3]=dx; f[4]=dy; f[5]=dz;
    if (j == n) {
        // self column: XLA's +0-init sum makes the dot +0 -> atan2(0,+0)=0 always.
        f[6] = 0.f; f[7] = 0.f; f[9] = 0.f;
    } else {
        f[6] = fangle(ax,ay,az, dx,dy,dz);
        f[7] = fangle(bx,by,bz, dx,dy,dz);
        f[9] = sqrtf(dx*dx + dy*dy + dz*dz);
    }
    f[8] = fangle(ax,ay,az, bx,by,bz);
    float* yp = g_y1 + (size_t)b*C1*MM + m;
#pragma unroll
    for (int o = 0; o < C1; o++) {
        float a = 0.f;
#pragma unroll
        for (int c = 0; c < 10; c++) a = fmaf(sW[o*10 + c], f[c], a);
        yp[(size_t)o * MM] = a;
    }
}

// ---------------- layer-0 stats ---------------------------------------------
__global__ void k_stats0() {
    __shared__ double rs[256], rq[256];
    const int id = blockIdx.x, q4 = id & 3, c = (id >> 2) % C1, b = id / (4*C1);
    const float* x = g_y1 + ((size_t)(b*C1) + c)*MM + (size_t)q4 * (MM/4);
    float s = 0.f, ss = 0.f;
    for (int i = threadIdx.x; i < MM/16; i += 256) {
        float4 v = ((const float4*)x)[i];
        s  += (v.x + v.y) + (v.z + v.w);
        ss += (v.x*v.x + v.y*v.y) + (v.z*v.z + v.w*v.w);
    }
    rs[threadIdx.x] = (double)s; rq[threadIdx.x] = (double)ss; __syncthreads();
    for (int st = 128; st; st >>= 1) {
        if (threadIdx.x < st) { rs[threadIdx.x] += rs[threadIdx.x+st]; rq[threadIdx.x] += rq[threadIdx.x+st]; }
        __syncthreads();
    }
    if (threadIdx.x == 0) {
        atomicAdd(&g_sd[0][(b*C1 + c)*2 + 0], rs[0]);
        atomicAdd(&g_sd[0][(b*C1 + c)*2 + 1], rq[0]);
    }
}

template<int C, int L>
__global__ void k_final() {
    int t = blockIdx.x * blockDim.x + threadIdx.x;
    if (t >= BB*C) return;
    const double inv = 1.0 / (double)MM;
    double mean = g_sd[L][2*t] * inv;
    double var  = g_sd[L][2*t+1] * inv - mean*mean;
    if (var < 0.0) var = 0.0;
    g_ms[L][2*t]   = (float)mean;
    g_ms[L][2*t+1] = (float)(1.0 / sqrt(var + 1e-5));
}

// ---------------- fused tf32 mma.sync GEMM -----------------------------------
// Block: 256 thr = 8 warps (4 row-groups x 2 col-groups). Tile = COUT x 64 cols
// (64 cols = one n). W resident in SMEM in fragment order; A tile = norm+relu(X)
// staged per tile in fragment order. LID1: store raw y2 + stats. LID2: max over
// the 64 cols (one n) + stats; y3 never materialized.
template<int CIN, int COUT, int LID>
__global__ void __launch_bounds__(256, 1) k_tgemm(const float* __restrict__ W) {
    constexpr int KS = CIN/8;            // k-steps of 8
    constexpr int RT = COUT/64;          // 16-row tiles per warp
    constexpr int TILES = 8;             // n-groups per block
    extern __shared__ __align__(16) uint32_t dsm[];
    uint32_t* WS = dsm;                  // [COUT/16][KS][32][4] frag-order tf32
    uint32_t* HS = dsm + COUT*CIN;       // [8][KS][32][2]      frag-order tf32
    __shared__ float sm_sum[256], sm_sq[256];
    __shared__ float sm_ms[512];
    __shared__ float sm_max[2][256];

    const int tid = threadIdx.x;
    const int lane = tid & 31, wid = tid >> 5;
    const int wrow = wid & 3, wcol = wid >> 2;
    const int b   = blockIdx.x >> 9;     // 512 blocks per batch
    const int blk = blockIdx.x & 511;

    if (tid < 256) { sm_sum[tid] = 0.f; sm_sq[tid] = 0.f; }
    for (int i = tid; i < CIN*2; i += 256) sm_ms[i] = g_ms[LID-1][b*CIN*2 + i];

    // stage W into fragment order (a0..a3 = {r,r+8} x {c,c+4})
    for (int idx = tid; idx < COUT*CIN; idx += 256) {
        int cout = idx / CIN, k = idx - cout*CIN;
        int rt = cout >> 4, r = cout & 15;
        int ks = k >> 3,   c = k & 7;
        int ln = ((r & 7) << 2) | (c & 3);
        int rg = (r >> 3) | ((c >> 2) << 1);
        WS[((rt*KS + ks)*32 + ln)*4 + rg] = f2tf32(W[idx]);
    }

    const float* Xb = ((LID == 1) ? g_y1 : g_y2) + (size_t)(b*CIN)*MM;

    float rsum[RT][2], rsq[RT][2];
#pragma unroll
    for (int i = 0; i < RT; i++) { rsum[i][0]=rsum[i][1]=0.f; rsq[i][0]=rsq[i][1]=0.f; }

    for (int t = 0; t < TILES; t++) {
        const int n  = blk*TILES + t;
        const int m0 = n*64;
        __syncthreads();                 // previous tile's HS readers done
        // stage A tile: norm + relu + tf32, B-fragment order (b0,b1 = k%4,{0,4}; n=l/4)
        for (int idx = tid; idx < CIN*64; idx += 256) {
            int k = idx >> 6, col = idx & 63;
            float v = Xb[(size_t)k*MM + m0 + col];
            v = fmaxf(0.f, (v - sm_ms[2*k]) * sm_ms[2*k+1]);
            int ks = k >> 3, r = k & 7;
            int ct = col >> 3, cl = col & 7;
            HS[((ct*KS + ks)*32 + ((cl<<2)|(r&3)))*2 + (r>>2)] = f2tf32(v);
        }
        __syncthreads();

        float d[RT][4][4];
#pragma unroll
        for (int i = 0; i < RT; i++)
#pragma unroll
            for (int ct = 0; ct < 4; ct++)
                { d[i][ct][0]=0.f; d[i][ct][1]=0.f; d[i][ct][2]=0.f; d[i][ct][3]=0.f; }

        for (int ks = 0; ks < KS; ks++) {
            uint32_t a[RT][4];
#pragma unroll
            for (int i = 0; i < RT; i++) {
                uint4 v4 = *(const uint4*)(WS + (((wrow*RT + i)*KS + ks)*32 + lane)*4);
                a[i][0]=v4.x; a[i][1]=v4.y; a[i][2]=v4.z; a[i][3]=v4.w;
            }
            uint32_t bf[4][2];
#pragma unroll
            for (int ct = 0; ct < 4; ct++) {
                uint2 v2 = *(const uint2*)(HS + (((wcol*4 + ct)*KS + ks)*32 + lane)*2);
                bf[ct][0]=v2.x; bf[ct][1]=v2.y;
            }
#pragma unroll
            for (int i = 0; i < RT; i++)
#pragma unroll
                for (int ct = 0; ct < 4; ct++)
                    mma1688(d[i][ct], a[i], bf[ct]);
        }

        if (LID == 1) {
#pragma unroll
            for (int i = 0; i < RT; i++) {
                int row0 = wrow*(COUT/4) + i*16 + (lane>>2);
#pragma unroll
                for (int ct = 0; ct < 4; ct++) {
                    int colb = m0 + wcol*32 + ct*8 + ((lane&3)<<1);
                    float2 lo = make_float2(d[i][ct][0], d[i][ct][1]);
                    float2 hi = make_float2(d[i][ct][2], d[i][ct][3]);
                    *(float2*)(g_y2 + ((size_t)(b*COUT)+row0  )*MM + colb) = lo;
                    *(float2*)(g_y2 + ((size_t)(b*COUT)+row0+8)*MM + colb) = hi;
                    rsum[i][0] += lo.x + lo.y; rsq[i][0] += lo.x*lo.x + lo.y*lo.y;
                    rsum[i][1] += hi.x + hi.y; rsq[i][1] += hi.x*hi.x + hi.y*hi.y;
                }
            }
        } else {
            float mv[RT][2];
#pragma unroll
            for (int i = 0; i < RT; i++) { mv[i][0] = -3.4e38f; mv[i][1] = -3.4e38f; }
#pragma unroll
            for (int i = 0; i < RT; i++)
#pragma unroll
                for (int ct = 0; ct < 4; ct++) {
                    float v0 = d[i][ct][0], v1 = d[i][ct][1];
                    float v2 = d[i][ct][2], v3 = d[i][ct][3];
                    mv[i][0] = fmaxf(mv[i][0], fmaxf(v0, v1));
                    mv[i][1] = fmaxf(mv[i][1], fmaxf(v2, v3));
                    rsum[i][0] += v0 + v1; rsq[i][0] += v0*v0 + v1*v1;
                    rsum[i][1] += v2 + v3; rsq[i][1] += v2*v2 + v3*v3;
                }
#pragma unroll
            for (int i = 0; i < RT; i++)
#pragma unroll
                for (int h = 0; h < 2; h++) {
                    float m = mv[i][h];
                    m = fmaxf(m, __shfl_xor_sync(0xffffffffu, m, 1));
                    m = fmaxf(m, __shfl_xor_sync(0xffffffffu, m, 2));
                    if ((lane & 3) == 0)
                        sm_max[wcol][wrow*(COUT/4) + i*16 + (lane>>2) + h*8] = m;
                }
            __syncthreads();
            if (tid < COUT)
                g_ymax[((size_t)b*NN + n)*C3 + tid] = fmaxf(sm_max[0][tid], sm_max[1][tid]);
        }
    }

    // stats flush: quad-reduce then smem, then one double atomic per channel
#pragma unroll
    for (int i = 0; i < RT; i++)
#pragma unroll
        for (int h = 0; h < 2; h++) {
            float s = rsum[i][h], q = rsq[i][h];
            s += __shfl_xor_sync(0xffffffffu, s, 1);
            s += __shfl_xor_sync(0xffffffffu, s, 2);
            q += __shfl_xor_sync(0xffffffffu, q, 1);
            q += __shfl_xor_sync(0xffffffffu, q, 2);
            if ((lane & 3) == 0) {
                int row = wrow*(COUT/4) + i*16 + (lane>>2) + h*8;
                atomicAdd(&sm_sum[row], s);
                atomicAdd(&sm_sq[row], q);
            }
        }
    __syncthreads();
    for (int i = tid; i < COUT; i += 256) {
        atomicAdd(&g_sd[LID][(b*COUT+i)*2+0], (double)sm_sum[i]);
        atomicAdd(&g_sd[LID][(b*COUT+i)*2+1], (double)sm_sq[i]);
    }
}

// ---------------- final output ------------------------------------------------
__global__ void k_out(float* __restrict__ out) {
    int t = blockIdx.x * 256 + threadIdx.x;          // b*C3*NN + cout*NN + n
    if (t >= BB*C3*NN) return;
    int bo = t >> 12, n = t & 4095;
    int b = bo >> 8, cout = bo & 255;
    float mean = g_ms[2][bo*2], istd = g_ms[2][bo*2 + 1];
    float v = (g_ymax[((size_t)b*NN + n)*C3 + cout] - mean) * istd;
    out[t] = fmaxf(v, 0.f);
}

// ---------------- launch -------------------------------------------------------
extern "C" void kernel_launch(void* const* d_in, const int* in_sizes, int n_in,
                              void* d_out, int out_size) {
    const float *big0 = nullptr, *big1 = nullptr, *W0 = nullptr, *W1 = nullptr, *W2 = nullptr;
    for (int i = 0; i < n_in; i++) {
        int sz = in_sizes[i];
        const float* p = (const float*)d_in[i];
        if (sz == BB*3*NN) { if (!big0) big0 = p; else big1 = p; }
        else if (sz == 64*10)   W0 = p;
        else if (sz == 128*64)  W1 = p;
        else if (sz == 256*128) W2 = p;
    }
    float* out = (float*)d_out;

    const int DSM1 = (C2*C1 + C1*64)*4;   // 48 KB
    const int DSM2 = (C3*C2 + C2*64)*4;   // 160 KB
    cudaFuncSetAttribute(k_tgemm<C1, C2, 1>, cudaFuncAttributeMaxDynamicSharedMemorySize, DSM1);
    cudaFuncSetAttribute(k_tgemm<C2, C3, 2>, cudaFuncAttributeMaxDynamicSharedMemorySize, DSM2);

    k_detect<<<1, 256>>>(big0);
    k_prep<<<32, 256>>>();
    k_knn<<<(BB*NN)/8, 256>>>(big0, big1);
    k_feat<<<(BB*MM)/128, 128>>>(big0, big1, W0);

    k_stats0<<<BB*C1*4, 256>>>();
    k_final<C1, 0><<<1, 256>>>();

    k_tgemm<C1, C2, 1><<<BB*512, 256, DSM1>>>(W1);
    k_final<C2, 1><<<2, 256>>>();

    k_tgemm<C2, C3, 2><<<BB*512, 256, DSM2>>>(W2);
    k_final<C3, 2><<<4, 256>>>();

    k_out<<<(BB*C3*NN)/256, 256>>>(out);
}

// round 11
// speedup vs baseline: 2.9763x; 1.5756x over previous
#include <cuda_runtime.h>
#include <cstdint>

#define BB 4
#define NN 4096
#define KK 64
#define MM (NN*KK)
#define C1 64
#define C2 128
#define C3 256

// ---------------- scratch ---------------------------------------------------
__device__ int    g_swap;
__device__ int    g_idx[BB*NN*KK];
__device__ float  g_y1[(size_t)BB*C1*MM];          // 256 MB raw layer-0 out
__device__ float  g_y2[(size_t)BB*C2*MM];          // 512 MB raw layer-1 out
__device__ float  g_ymax[(size_t)BB*NN*C3];        // 16 MB  max_k raw layer-2, [b][n][cout]
__device__ double g_sd[3][BB*C3*2];                // sum,sumsq per layer
__device__ float  g_ms[3][BB*C3*2];                // mean,istd per layer

// ---------------- helpers ----------------------------------------------------
__device__ __forceinline__ uint32_t f2tf32(float f) {
    uint32_t r; asm("cvt.rna.tf32.f32 %0, %1;" : "=r"(r) : "f"(f)); return r;
}
__device__ __forceinline__ void mma1688(float* d, const uint32_t* a, const uint32_t* b) {
    asm volatile(
      "mma.sync.aligned.m16n8k8.row.col.f32.tf32.tf32.f32 "
      "{%0,%1,%2,%3}, {%4,%5,%6,%7}, {%8,%9}, {%0,%1,%2,%3};"
      : "+f"(d[0]), "+f"(d[1]), "+f"(d[2]), "+f"(d[3])
      : "r"(a[0]), "r"(a[1]), "r"(a[2]), "r"(a[3]), "r"(b[0]), "r"(b[1]));
}

// ---------------- input detect / prep ---------------------------------------
__global__ void k_detect(const float* __restrict__ a) {
    __shared__ int neg;
    if (threadIdx.x == 0) neg = 0;
    __syncthreads();
    int f = 0;
    for (int i = threadIdx.x; i < BB*3*NN; i += 256) if (a[i] < 0.f) f = 1;
    if (f) neg = 1;
    __syncthreads();
    if (threadIdx.x == 0) g_swap = neg;
}

__global__ void k_prep() {
    int t = blockIdx.x * blockDim.x + threadIdx.x;
    if (t < 3*BB*C3*2) (&g_sd[0][0])[t] = 0.0;
}

// ---------------- KNN: warp-ballot per point ---------------------------------
__global__ void k_knn(const float* __restrict__ cA, const float* __restrict__ cB) {
    const float* coords = g_swap ? cB : cA;
    __shared__ float sx[NN], sy[NN], sz[NN];
    const int warp = threadIdx.x >> 5, lane = threadIdx.x & 31;
    const int pid = blockIdx.x * 8 + warp;
    const int b = pid >> 12, n = pid & (NN - 1);
    const float* cb = coords + (size_t)b * 3 * NN;
    for (int i = threadIdx.x; i < NN; i += blockDim.x) {
        sx[i] = cb[i]; sy[i] = cb[NN + i]; sz[i] = cb[2*NN + i];
    }
    __syncthreads();
    const float px = sx[n], py = sy[n], pz = sz[n];
    int cnt = 0, j0 = 0;
    int* out = g_idx + (size_t)pid * KK;
    for (int base = 0; base < NN; base += 32) {
        int j = base + lane;
        float dx = sx[j] - px, dy = sy[j] - py, dz = sz[j] - pz;
        float d2 = __fadd_rn(__fadd_rn(__fmul_rn(dx,dx), __fmul_rn(dy,dy)), __fmul_rn(dz,dz));
        bool valid = !(d2 > 0.04f);
        unsigned m = __ballot_sync(0xffffffffu, valid);
        if (cnt == 0 && m) j0 = base + (__ffs(m) - 1);
        int pos = cnt + __popc(m & ((1u << lane) - 1u));
        if (valid && pos < KK) out[pos] = j;
        cnt += __popc(m);
        if (cnt >= KK) break;
    }
    if (cnt < KK)
        for (int t = cnt + lane; t < KK; t += 32) out[t] = j0;
}

// ---------------- features + layer-0 (10 -> 64) -----------------------------
__device__ __forceinline__ float fangle(float ax,float ay,float az,
                                        float bx,float by,float bz) {
    float cx = ay*bz - az*by, cy = az*bx - ax*bz, cz = ax*by - ay*bx;
    return atan2f(sqrtf(cx*cx + cy*cy + cz*cz), ax*bx + ay*by + az*bz);
}

__global__ void k_feat(const float* __restrict__ cA, const float* __restrict__ cB,
                       const float* __restrict__ W0) {
    const float* coords = g_swap ? cB : cA;
    const float* feats  = g_swap ? cA : cB;
    __shared__ float sW[C1*10];
    for (int i = threadIdx.x; i < C1*10; i += blockDim.x) sW[i] = W0[i];
    __syncthreads();
    const int gid = blockIdx.x * blockDim.x + threadIdx.x;
    const int b = gid >> 18, m = gid & (MM - 1);
    const int n = m >> 6, k = m & 63;
    const float* cb = coords + (size_t)b * 3 * NN;
    const float* fb = feats  + (size_t)b * 3 * NN;
    const float px = cb[n], py = cb[NN+n], pz = cb[2*NN+n];
    const float ax = fb[n], ay = fb[NN+n], az = fb[2*NN+n];
    const int j = g_idx[((size_t)(b*NN + n))*KK + k];
    const float dx = cb[j]-px, dy = cb[NN+j]-py, dz = cb[2*NN+j]-pz;
    const float bx = fb[j], by = fb[NN+j], bz = fb[2*NN+j];
    float f[10];
    f[0]=px; f[1]=py; f[2]=pz; f[3]=dx; f[4]=dy; f[5]=dz;
    if (j == n) {
        // self column: XLA's +0-init sum makes the dot +0 -> atan2(0,+0)=0 always.
        f[6] = 0.f; f[7] = 0.f; f[9] = 0.f;
    } else {
        f[6] = fangle(ax,ay,az, dx,dy,dz);
        f[7] = fangle(bx,by,bz, dx,dy,dz);
        f[9] = sqrtf(dx*dx + dy*dy + dz*dz);
    }
    f[8] = fangle(ax,ay,az, bx,by,bz);
    float* yp = g_y1 + (size_t)b*C1*MM + m;
#pragma unroll
    for (int o = 0; o < C1; o++) {
        float a = 0.f;
#pragma unroll
        for (int c = 0; c < 10; c++) a = fmaf(sW[o*10 + c], f[c], a);
        yp[(size_t)o * MM] = a;
    }
}

// ---------------- layer-0 stats ---------------------------------------------
__global__ void k_stats0() {
    __shared__ double rs[256], rq[256];
    const int id = blockIdx.x, q4 = id & 3, c = (id >> 2) % C1, b = id / (4*C1);
    const float* x = g_y1 + ((size_t)(b*C1) + c)*MM + (size_t)q4 * (MM/4);
    float s = 0.f, ss = 0.f;
    for (int i = threadIdx.x; i < MM/16; i += 256) {
        float4 v = ((const float4*)x)[i];
        s  += (v.x + v.y) + (v.z + v.w);
        ss += (v.x*v.x + v.y*v.y) + (v.z*v.z + v.w*v.w);
    }
    rs[threadIdx.x] = (double)s; rq[threadIdx.x] = (double)ss; __syncthreads();
    for (int st = 128; st; st >>= 1) {
        if (threadIdx.x < st) { rs[threadIdx.x] += rs[threadIdx.x+st]; rq[threadIdx.x] += rq[threadIdx.x+st]; }
        __syncthreads();
    }
    if (threadIdx.x == 0) {
        atomicAdd(&g_sd[0][(b*C1 + c)*2 + 0], rs[0]);
        atomicAdd(&g_sd[0][(b*C1 + c)*2 + 1], rq[0]);
    }
}

template<int C, int L>
__global__ void k_final() {
    int t = blockIdx.x * blockDim.x + threadIdx.x;
    if (t >= BB*C) return;
    const double inv = 1.0 / (double)MM;
    double mean = g_sd[L][2*t] * inv;
    double var  = g_sd[L][2*t+1] * inv - mean*mean;
    if (var < 0.0) var = 0.0;
    g_ms[L][2*t]   = (float)mean;
    g_ms[L][2*t+1] = (float)(1.0 / sqrt(var + 1e-5));
}

// ---------------- fused tf32 mma.sync GEMM, prefetch + ping-pong -------------
// Block: 256 thr = 8 warps (4 row x 2 col). Tile = COUT x 64 cols (one n).
// pf regs hold next tile's raw X while MMAs run on current tile.
template<int CIN, int COUT, int LID, int MINB>
__global__ void __launch_bounds__(256, MINB) k_tgemm(const float* __restrict__ W) {
    constexpr int KS = CIN/8;            // k-steps of 8
    constexpr int RT = COUT/64;          // 16-row tiles per warp
    constexpr int TILES = 8;             // n-groups per block
    constexpr int NR = CIN*64/256;       // prefetch floats per thread
    constexpr int HSN = CIN*64;          // words per HS buffer
    extern __shared__ __align__(16) uint32_t dsm[];
    uint32_t* WS = dsm;                  // [COUT/16][KS][32][4] frag-order tf32
    uint32_t* HS = dsm + COUT*CIN;       // 2 x [8][KS][32][2]   frag-order tf32
    __shared__ float sm_sum[256], sm_sq[256];
    __shared__ float sm_ms[512];
    __shared__ float sm_max[2][256];

    const int tid = threadIdx.x;
    const int lane = tid & 31, wid = tid >> 5;
    const int wrow = wid & 3, wcol = wid >> 2;
    const int b   = blockIdx.x >> 9;     // 512 blocks per batch
    const int blk = blockIdx.x & 511;

    if (tid < 256) { sm_sum[tid] = 0.f; sm_sq[tid] = 0.f; }
    for (int i = tid; i < CIN*2; i += 256) sm_ms[i] = g_ms[LID-1][b*CIN*2 + i];

    // stage W into fragment order (a0..a3 = {r,r+8} x {c,c+4})
    for (int idx = tid; idx < COUT*CIN; idx += 256) {
        int cout = idx / CIN, k = idx - cout*CIN;
        int rt = cout >> 4, r = cout & 15;
        int ks = k >> 3,   c = k & 7;
        int ln = ((r & 7) << 2) | (c & 3);
        int rg = (r >> 3) | ((c >> 2) << 1);
        WS[((rt*KS + ks)*32 + ln)*4 + rg] = f2tf32(W[idx]);
    }

    const float* Xb = ((LID == 1) ? g_y1 : g_y2) + (size_t)(b*CIN)*MM;
    const int krow0 = tid >> 6;          // base k row for this thread
    const int col   = tid & 63;

    float rsum[RT][2], rsq[RT][2];
#pragma unroll
    for (int i = 0; i < RT; i++) { rsum[i][0]=rsum[i][1]=0.f; rsq[i][0]=rsq[i][1]=0.f; }

    // prefetch tile 0
    float pf[NR];
    {
        const int m0 = blk*TILES*64;
#pragma unroll
        for (int i = 0; i < NR; i++)
            pf[i] = Xb[(size_t)(krow0 + i*4)*MM + m0 + col];
    }
    __syncthreads();                     // WS + sm_ms ready

    for (int t = 0; t < TILES; t++) {
        const int n  = blk*TILES + t;
        const int m0 = n*64;
        uint32_t* HB = HS + (t & 1)*HSN;

        // normalize + relu + tf32 from prefetch regs into fragment order
#pragma unroll
        for (int i = 0; i < NR; i++) {
            int k = krow0 + i*4;
            float v = fmaxf(0.f, (pf[i] - sm_ms[2*k]) * sm_ms[2*k+1]);
            int ks = k >> 3, r = k & 7;
            int ct = col >> 3, cl = col & 7;
            HB[((ct*KS + ks)*32 + ((cl<<2)|(r&3)))*2 + (r>>2)] = f2tf32(v);
        }
        __syncthreads();

        // prefetch next tile while MMAs run
        if (t + 1 < TILES) {
            const int m1 = m0 + 64;
#pragma unroll
            for (int i = 0; i < NR; i++)
                pf[i] = Xb[(size_t)(krow0 + i*4)*MM + m1 + col];
        }

        float d[RT][4][4];
#pragma unroll
        for (int i = 0; i < RT; i++)
#pragma unroll
            for (int ct = 0; ct < 4; ct++)
                { d[i][ct][0]=0.f; d[i][ct][1]=0.f; d[i][ct][2]=0.f; d[i][ct][3]=0.f; }

        for (int ks = 0; ks < KS; ks++) {
            uint32_t a[RT][4];
#pragma unroll
            for (int i = 0; i < RT; i++) {
                uint4 v4 = *(const uint4*)(WS + (((wrow*RT + i)*KS + ks)*32 + lane)*4);
                a[i][0]=v4.x; a[i][1]=v4.y; a[i][2]=v4.z; a[i][3]=v4.w;
            }
            uint32_t bf[4][2];
#pragma unroll
            for (int ct = 0; ct < 4; ct++) {
                uint2 v2 = *(const uint2*)(HB + (((wcol*4 + ct)*KS + ks)*32 + lane)*2);
                bf[ct][0]=v2.x; bf[ct][1]=v2.y;
            }
#pragma unroll
            for (int i = 0; i < RT; i++)
#pragma unroll
                for (int ct = 0; ct < 4; ct++)
                    mma1688(d[i][ct], a[i], bf[ct]);
        }

        if (LID == 1) {
#pragma unroll
            for (int i = 0; i < RT; i++) {
                int row0 = wrow*(COUT/4) + i*16 + (lane>>2);
#pragma unroll
                for (int ct = 0; ct < 4; ct++) {
                    int colb = m0 + wcol*32 + ct*8 + ((lane&3)<<1);
                    float2 lo = make_float2(d[i][ct][0], d[i][ct][1]);
                    float2 hi = make_float2(d[i][ct][2], d[i][ct][3]);
                    *(float2*)(g_y2 + ((size_t)(b*COUT)+row0  )*MM + colb) = lo;
                    *(float2*)(g_y2 + ((size_t)(b*COUT)+row0+8)*MM + colb) = hi;
                    rsum[i][0] += lo.x + lo.y; rsq[i][0] += lo.x*lo.x + lo.y*lo.y;
                    rsum[i][1] += hi.x + hi.y; rsq[i][1] += hi.x*hi.x + hi.y*hi.y;
                }
            }
        } else {
            float mv[RT][2];
#pragma unroll
            for (int i = 0; i < RT; i++) { mv[i][0] = -3.4e38f; mv[i][1] = -3.4e38f; }
#pragma unroll
            for (int i = 0; i < RT; i++)
#pragma unroll
                for (int ct = 0; ct < 4; ct++) {
                    float v0 = d[i][ct][0], v1 = d[i][ct][1];
                    float v2 = d[i][ct][2], v3 = d[i][ct][3];
                    mv[i][0] = fmaxf(mv[i][0], fmaxf(v0, v1));
                    mv[i][1] = fmaxf(mv[i][1], fmaxf(v2, v3));
                    rsum[i][0] += v0 + v1; rsq[i][0] += v0*v0 + v1*v1;
                    rsum[i][1] += v2 + v3; rsq[i][1] += v2*v2 + v3*v3;
                }
#pragma unroll
            for (int i = 0; i < RT; i++)
#pragma unroll
                for (int h = 0; h < 2; h++) {
                    float m = mv[i][h];
                    m = fmaxf(m, __shfl_xor_sync(0xffffffffu, m, 1));
                    m = fmaxf(m, __shfl_xor_sync(0xffffffffu, m, 2));
                    if ((lane & 3) == 0)
                        sm_max[wcol][wrow*(COUT/4) + i*16 + (lane>>2) + h*8] = m;
                }
            __syncthreads();
            if (tid < COUT)
                g_ymax[((size_t)b*NN + n)*C3 + tid] = fmaxf(sm_max[0][tid], sm_max[1][tid]);
        }
    }

    // stats flush: quad-reduce then smem, then one double atomic per channel
#pragma unroll
    for (int i = 0; i < RT; i++)
#pragma unroll
        for (int h = 0; h < 2; h++) {
            float s = rsum[i][h], q = rsq[i][h];
            s += __shfl_xor_sync(0xffffffffu, s, 1);
            s += __shfl_xor_sync(0xffffffffu, s, 2);
            q += __shfl_xor_sync(0xffffffffu, q, 1);
            q += __shfl_xor_sync(0xffffffffu, q, 2);
            if ((lane & 3) == 0) {
                int row = wrow*(COUT/4) + i*16 + (lane>>2) + h*8;
                atomicAdd(&sm_sum[row], s);
                atomicAdd(&sm_sq[row], q);
            }
        }
    __syncthreads();
    for (int i = tid; i < COUT; i += 256) {
        atomicAdd(&g_sd[LID][(b*COUT+i)*2+0], (double)sm_sum[i]);
        atomicAdd(&g_sd[LID][(b*COUT+i)*2+1], (double)sm_sq[i]);
    }
}

// ---------------- final output: coalesced transpose ---------------------------
__global__ void k_out(float* __restrict__ out) {
    __shared__ float sm[32][257];
    const int tid = threadIdx.x, lane = tid & 31, wid = tid >> 5;
    const int b = blockIdx.x >> 7;               // 128 blocks per batch
    const int n0 = (blockIdx.x & 127) * 32;
#pragma unroll 4
    for (int i = 0; i < 32; i++)
        sm[i][tid] = g_ymax[((size_t)b*NN + n0 + i)*C3 + tid];
    __syncthreads();
#pragma unroll 4
    for (int j = 0; j < 32; j++) {
        int cout = j*8 + wid;
        float mean = g_ms[2][(b*C3 + cout)*2], istd = g_ms[2][(b*C3 + cout)*2 + 1];
        float v = (sm[lane][cout] - mean) * istd;
        out[((size_t)(b*C3) + cout)*NN + n0 + lane] = fmaxf(v, 0.f);
    }
}

// ---------------- launch -------------------------------------------------------
extern "C" void kernel_launch(void* const* d_in, const int* in_sizes, int n_in,
                              void* d_out, int out_size) {
    const float *big0 = nullptr, *big1 = nullptr, *W0 = nullptr, *W1 = nullptr, *W2 = nullptr;
    for (int i = 0; i < n_in; i++) {
        int sz = in_sizes[i];
        const float* p = (const float*)d_in[i];
        if (sz == BB*3*NN) { if (!big0) big0 = p; else big1 = p; }
        else if (sz == 64*10)   W0 = p;
        else if (sz == 128*64)  W1 = p;
        else if (sz == 256*128) W2 = p;
    }
    float* out = (float*)d_out;

    const int DSM1 = (C2*C1 + 2*C1*64)*4;   // 64 KB (W + 2x ping-pong A)
    const int DSM2 = (C3*C2 + 2*C2*64)*4;   // 192 KB
    cudaFuncSetAttribute(k_tgemm<C1, C2, 1, 2>, cudaFuncAttributeMaxDynamicSharedMemorySize, DSM1);
    cudaFuncSetAttribute(k_tgemm<C2, C3, 2, 1>, cudaFuncAttributeMaxDynamicSharedMemorySize, DSM2);

    k_detect<<<1, 256>>>(big0);
    k_prep<<<32, 256>>>();
    k_knn<<<(BB*NN)/8, 256>>>(big0, big1);
    k_feat<<<(BB*MM)/128, 128>>>(big0, big1, W0);

    k_stats0<<<BB*C1*4, 256>>>();
    k_final<C1, 0><<<1, 256>>>();

    k_tgemm<C1, C2, 1, 2><<<BB*512, 256, DSM1>>>(W1);
    k_final<C2, 1><<<2, 256>>>();

    k_tgemm<C2, C3, 2, 1><<<BB*512, 256, DSM2>>>(W2);
    k_final<C3, 2><<<4, 256>>>();

    k_out<<<BB*128, 256>>>(out);
}